// round 2
// baseline (speedup 1.0000x reference)
#include <cuda_runtime.h>
#include <cuda_bf16.h>

#define N       8192
#define D       128
#define BM      128
#define BN      128
#define SPLITS  4
#define NTILES  (N / BN / SPLITS)   // 16 column tiles per split
#define P       16
#define MARGINF 1.0f
#define EPSF    1e-12f
#define FINF    __int_as_float(0x7f800000)

// Scratch (no allocation allowed -> device globals)
__device__ float g_sq[N];
__device__ float g_maxp[SPLITS][N];
__device__ float g_minn[SPLITS][N];
__device__ float g_cn[P * D];
__device__ float g_partials[N / 16];

// ---------------------------------------------------------------------------
// Row squared norms: one warp per row, coalesced float4 loads.
__global__ void k_sqnorm(const float* __restrict__ X) {
    int w = (blockIdx.x * blockDim.x + threadIdx.x) >> 5;
    int lane = threadIdx.x & 31;
    if (w >= N) return;
    const float4* x4 = (const float4*)X + (size_t)w * (D / 4);
    float4 v = x4[lane];
    float s = v.x * v.x + v.y * v.y + v.z * v.z + v.w * v.w;
    #pragma unroll
    for (int o = 16; o; o >>= 1) s += __shfl_xor_sync(0xffffffffu, s, o);
    if (lane == 0) g_sq[w] = s;
}

// ---------------------------------------------------------------------------
// Normalize centers: one warp per prototype.
__global__ void k_prep(const float* __restrict__ C) {
    int w = threadIdx.x >> 5;
    int lane = threadIdx.x & 31;
    if (w >= P) return;
    const float4* c4 = (const float4*)(C + (size_t)w * D);
    float4 v = c4[lane];
    float s = v.x * v.x + v.y * v.y + v.z * v.z + v.w * v.w;
    #pragma unroll
    for (int o = 16; o; o >>= 1) s += __shfl_xor_sync(0xffffffffu, s, o);
    float inv = 1.0f / sqrtf(s);
    float* dst = g_cn + (size_t)w * D + lane * 4;
    dst[0] = v.x * inv; dst[1] = v.y * inv; dst[2] = v.z * inv; dst[3] = v.w * inv;
}

// ---------------------------------------------------------------------------
// Main mining kernel: block = 128 rows x (N/SPLITS) cols streamed in 128-wide
// tiles. 256 threads, 8x8 register tile each. Squared-distance mining only.
// NOTE: targets are int32 (JAX default config downcasts jnp.int64 requests).
__global__ void __launch_bounds__(256, 1)
k_main(const float* __restrict__ X, const int* __restrict__ T) {
    extern __shared__ float sm[];
    float* As = sm;                 // [D][BM], k-major
    float* Bs = sm + D * BM;        // [D][BN], k-major
    __shared__ int   tRow[BM];
    __shared__ int   tCol[BN];
    __shared__ float sqCol[BN];

    const int tid   = threadIdx.x;
    const int row0  = blockIdx.x * BM;
    const int split = blockIdx.y;
    const float4* X4 = (const float4*)X;

    // Load A tile transposed into k-major smem.
    for (int i = tid; i < BM * (D / 4); i += 256) {
        int k4 = i >> 7;            // 0..31
        int r  = i & (BM - 1);      // 0..127, consecutive across threads
        float4 v = X4[(size_t)(row0 + r) * (D / 4) + k4];
        As[(4 * k4 + 0) * BM + r] = v.x;
        As[(4 * k4 + 1) * BM + r] = v.y;
        As[(4 * k4 + 2) * BM + r] = v.z;
        As[(4 * k4 + 3) * BM + r] = v.w;
    }
    if (tid < BM) tRow[tid] = T[row0 + tid];
    __syncthreads();

    const int tx = tid & 15, ty = tid >> 4;
    const int r0 = ty * 8, c0 = tx * 8;

    float sqr[8];
    int   tr[8];
    #pragma unroll
    for (int i = 0; i < 8; i++) {
        sqr[i] = g_sq[row0 + r0 + i];
        tr[i]  = tRow[r0 + i];
    }

    float maxp[8], minn[8];
    #pragma unroll
    for (int i = 0; i < 8; i++) { maxp[i] = -1.0f; minn[i] = FINF; }

    for (int t = 0; t < NTILES; t++) {
        int col0 = split * (N / SPLITS) + t * BN;
        __syncthreads();            // previous tile's compute done before overwrite
        for (int i = tid; i < BN * (D / 4); i += 256) {
            int k4 = i >> 7;
            int r  = i & (BN - 1);
            float4 v = X4[(size_t)(col0 + r) * (D / 4) + k4];
            Bs[(4 * k4 + 0) * BN + r] = v.x;
            Bs[(4 * k4 + 1) * BN + r] = v.y;
            Bs[(4 * k4 + 2) * BN + r] = v.z;
            Bs[(4 * k4 + 3) * BN + r] = v.w;
        }
        if (tid < BN) { tCol[tid] = T[col0 + tid]; sqCol[tid] = g_sq[col0 + tid]; }
        __syncthreads();

        float acc[8][8];
        #pragma unroll
        for (int i = 0; i < 8; i++)
            #pragma unroll
            for (int j = 0; j < 8; j++) acc[i][j] = 0.0f;

        #pragma unroll 4
        for (int k = 0; k < D; k++) {
            float4 a0 = *(const float4*)&As[k * BM + r0];
            float4 a1 = *(const float4*)&As[k * BM + r0 + 4];
            float4 b0 = *(const float4*)&Bs[k * BN + c0];
            float4 b1 = *(const float4*)&Bs[k * BN + c0 + 4];
            float a[8] = {a0.x, a0.y, a0.z, a0.w, a1.x, a1.y, a1.z, a1.w};
            float b[8] = {b0.x, b0.y, b0.z, b0.w, b1.x, b1.y, b1.z, b1.w};
            #pragma unroll
            for (int ri = 0; ri < 8; ri++)
                #pragma unroll
                for (int ci = 0; ci < 8; ci++)
                    acc[ri][ci] = fmaf(a[ri], b[ci], acc[ri][ci]);
        }

        // Mining on squared distances (sqrt is monotone -> defer it).
        #pragma unroll
        for (int ci = 0; ci < 8; ci++) {
            int   tc  = tCol[c0 + ci];
            float sqc = sqCol[c0 + ci];
            #pragma unroll
            for (int ri = 0; ri < 8; ri++) {
                float d2 = fmaxf(fmaf(-2.0f, acc[ri][ci], sqr[ri] + sqc), 0.0f);
                if (tr[ri] == tc) maxp[ri] = fmaxf(maxp[ri], d2);
                else              minn[ri] = fminf(minn[ri], d2);
            }
        }
    }

    // Cross-tx reduction (reuse As region as [BM][16] scratch).
    __syncthreads();
    float* red = sm;
    #pragma unroll
    for (int i = 0; i < 8; i++) red[(r0 + i) * 16 + tx] = maxp[i];
    __syncthreads();
    if (tid < BM) {
        float m = -1.0f;
        #pragma unroll
        for (int j = 0; j < 16; j++) m = fmaxf(m, red[tid * 16 + j]);
        g_maxp[split][row0 + tid] = m;
    }
    __syncthreads();
    #pragma unroll
    for (int i = 0; i < 8; i++) red[(r0 + i) * 16 + tx] = minn[i];
    __syncthreads();
    if (tid < BM) {
        float m = FINF;
        #pragma unroll
        for (int j = 0; j < 16; j++) m = fminf(m, red[tid * 16 + j]);
        g_minn[split][row0 + tid] = m;
    }
}

// ---------------------------------------------------------------------------
// Finalize: 16 rows/block; thread (r,c) computes distance row r -> center c,
// min-reduce over 16 centers, combine with mined max/min, per-block sum.
__global__ void k_finalize(const float* __restrict__ X) {
    __shared__ float xs[16 * D];
    __shared__ float cnt[D * 16];   // transposed [k][c] -> conflict-free
    __shared__ float terms[16];
    const int b = blockIdx.x, tid = threadIdx.x;
    const int row0 = b * 16;

    for (int i = tid; i < 16 * D; i += 256) xs[i] = X[(size_t)row0 * D + i];
    for (int i = tid; i < P * D; i += 256) {
        int k = i >> 4, c = i & 15;
        cnt[k * 16 + c] = g_cn[c * D + k];
    }
    __syncthreads();

    const int r = tid >> 4, c = tid & 15;
    float d2 = 0.0f;
    #pragma unroll 8
    for (int k = 0; k < D; k++) {
        float diff = xs[r * D + k] - cnt[k * 16 + c];
        d2 = fmaf(diff, diff, d2);
    }
    float dc = fmaxf(sqrtf(d2), EPSF);
    #pragma unroll
    for (int o = 8; o; o >>= 1) dc = fminf(dc, __shfl_xor_sync(0xffffffffu, dc, o));

    if (c == 0) {
        int row = row0 + r;
        float mp = -1.0f, mn = FINF;
        #pragma unroll
        for (int s = 0; s < SPLITS; s++) {
            mp = fmaxf(mp, g_maxp[s][row]);
            mn = fminf(mn, g_minn[s][row]);
        }
        float dap = sqrtf(fmaxf(mp, EPSF));
        float dan = isinf(mn) ? (dap + MARGINF) : sqrtf(fmaxf(mn, EPSF));
        dan = fminf(dan, dc);
        terms[r] = fmaxf(dap - dan + MARGINF, 0.0f);
    }
    __syncthreads();
    if (tid == 0) {
        float s = 0.0f;
        #pragma unroll
        for (int i = 0; i < 16; i++) s += terms[i];
        g_partials[b] = s;
    }
}

// ---------------------------------------------------------------------------
// Deterministic tree sum of 512 partials -> mean.
__global__ void k_sum(float* __restrict__ out) {
    __shared__ float sh[512];
    int t = threadIdx.x;
    sh[t] = g_partials[t];
    __syncthreads();
    for (int s = 256; s; s >>= 1) {
        if (t < s) sh[t] += sh[t + s];
        __syncthreads();
    }
    if (t == 0) out[0] = sh[0] / (float)N;
}

// ---------------------------------------------------------------------------
extern "C" void kernel_launch(void* const* d_in, const int* in_sizes, int n_in,
                              void* d_out, int out_size) {
    const float* X = (const float*)d_in[0];
    const int*   T = (const int*)d_in[1];
    const float* C = (const float*)d_in[2];
    float* out = (float*)d_out;

    size_t smem = (size_t)(2 * D * BM) * sizeof(float);   // 128 KB
    cudaFuncSetAttribute(k_main, cudaFuncAttributeMaxDynamicSharedMemorySize, (int)smem);

    k_sqnorm<<<N / 8, 256>>>(X);
    k_prep<<<1, P * 32>>>(C);
    k_main<<<dim3(N / BM, SPLITS), 256, smem>>>(X, T);
    k_finalize<<<N / 16, 256>>>(X);
    k_sum<<<1, 512>>>(out);
}

// round 4
// speedup vs baseline: 2.5238x; 2.5238x over previous
#include <cuda_runtime.h>
#include <cuda_bf16.h>
#include <cstdint>

#define N       8192
#define D       128
#define BM      128
#define BN      128
#define SPLITS  4
#define NTILES  (N / BN / SPLITS)   // 16 column tiles per split
#define P       16
#define MARGINF 1.0f
#define EPSF    1e-12f
#define FINF    __int_as_float(0x7f800000)

// smem layout (dynamic, 192KB): A hi | A lo | B buf0 (hi|lo) | B buf1 (hi|lo)
#define SMA_HI  0u
#define SMA_LO  32768u
#define SMB0    65536u
#define SMB_SZ  65536u      // hi 32KB + lo 32KB per buffer

// Scratch (no allocation allowed -> device globals)
__device__ float g_sq[N];
__device__ float g_maxp[SPLITS][N];
__device__ float g_minn[SPLITS][N];
__device__ float g_cn[P * D];
__device__ float g_partials[N / 16];
__device__ __nv_bfloat16 g_xhi[N * D];
__device__ __nv_bfloat16 g_xlo[N * D];

// ---------------------------------------------------------------------------
static __device__ __forceinline__ uint32_t smem_u32(const void* p) {
    uint32_t a;
    asm("{ .reg .u64 t; cvta.to.shared.u64 t, %1; cvt.u32.u64 %0, t; }" : "=r"(a) : "l"(p));
    return a;
}
static __device__ __forceinline__ void ldsm4(uint32_t* r, uint32_t addr) {
    asm volatile("ldmatrix.sync.aligned.m8n8.x4.shared.b16 {%0,%1,%2,%3}, [%4];"
                 : "=r"(r[0]), "=r"(r[1]), "=r"(r[2]), "=r"(r[3]) : "r"(addr));
}
static __device__ __forceinline__ void mma16816(float* c, const uint32_t* a,
                                                const uint32_t* b) {
    asm volatile("mma.sync.aligned.m16n8k16.row.col.f32.bf16.bf16.f32 "
                 "{%0,%1,%2,%3}, {%4,%5,%6,%7}, {%8,%9}, {%0,%1,%2,%3};"
                 : "+f"(c[0]), "+f"(c[1]), "+f"(c[2]), "+f"(c[3])
                 : "r"(a[0]), "r"(a[1]), "r"(a[2]), "r"(a[3]), "r"(b[0]), "r"(b[1]));
}
static __device__ __forceinline__ void cpa16(uint32_t dst, const void* src) {
    asm volatile("cp.async.cg.shared.global [%0], [%1], 16;" :: "r"(dst), "l"(src) : "memory");
}
#define CPA_COMMIT() asm volatile("cp.async.commit_group;" ::: "memory")
#define CPA_WAIT(n)  asm volatile("cp.async.wait_group %0;" :: "n"(n) : "memory")

// 128x128 bf16 tile -> smem, row-major 256B rows, 16B-chunk xor swizzle.
static __device__ __forceinline__ void cpa_tile(uint32_t dst_s,
                                                const __nv_bfloat16* src,
                                                int row0, int tid) {
    const char* base = (const char*)(src + (size_t)row0 * D);
    #pragma unroll
    for (int i = 0; i < 8; i++) {
        int idx = tid + i * 256;
        int r = idx >> 4, c = idx & 15;
        uint32_t off = (uint32_t)r * 256 + (uint32_t)((c ^ (r & 7)) << 4);
        cpa16(dst_s + off, base + (size_t)r * 256 + c * 16);
    }
}

// ---------------------------------------------------------------------------
// Split fp32 -> bf16 hi/lo pair (hi = rn(x), lo = rn(x - hi)).
__global__ void k_split(const float* __restrict__ X) {
    int i = blockIdx.x * blockDim.x + threadIdx.x;
    float4 v = ((const float4*)X)[i];
    __nv_bfloat16 h0 = __float2bfloat16(v.x), h1 = __float2bfloat16(v.y);
    __nv_bfloat16 h2 = __float2bfloat16(v.z), h3 = __float2bfloat16(v.w);
    __nv_bfloat16 l0 = __float2bfloat16(v.x - __bfloat162float(h0));
    __nv_bfloat16 l1 = __float2bfloat16(v.y - __bfloat162float(h1));
    __nv_bfloat16 l2 = __float2bfloat16(v.z - __bfloat162float(h2));
    __nv_bfloat16 l3 = __float2bfloat16(v.w - __bfloat162float(h3));
    ((__nv_bfloat162*)g_xhi)[2*i]   = __nv_bfloat162(h0, h1);
    ((__nv_bfloat162*)g_xhi)[2*i+1] = __nv_bfloat162(h2, h3);
    ((__nv_bfloat162*)g_xlo)[2*i]   = __nv_bfloat162(l0, l1);
    ((__nv_bfloat162*)g_xlo)[2*i+1] = __nv_bfloat162(l2, l3);
}

__global__ void k_sqnorm(const float* __restrict__ X) {
    int w = (blockIdx.x * blockDim.x + threadIdx.x) >> 5;
    int lane = threadIdx.x & 31;
    if (w >= N) return;
    const float4* x4 = (const float4*)X + (size_t)w * (D / 4);
    float4 v = x4[lane];
    float s = v.x * v.x + v.y * v.y + v.z * v.z + v.w * v.w;
    #pragma unroll
    for (int o = 16; o; o >>= 1) s += __shfl_xor_sync(0xffffffffu, s, o);
    if (lane == 0) g_sq[w] = s;
}

__global__ void k_prep(const float* __restrict__ C) {
    int w = threadIdx.x >> 5;
    int lane = threadIdx.x & 31;
    if (w >= P) return;
    const float4* c4 = (const float4*)(C + (size_t)w * D);
    float4 v = c4[lane];
    float s = v.x * v.x + v.y * v.y + v.z * v.z + v.w * v.w;
    #pragma unroll
    for (int o = 16; o; o >>= 1) s += __shfl_xor_sync(0xffffffffu, s, o);
    float inv = 1.0f / sqrtf(s);
    float* dst = g_cn + (size_t)w * D + lane * 4;
    dst[0] = v.x * inv; dst[1] = v.y * inv; dst[2] = v.z * inv; dst[3] = v.w * inv;
}

// ---------------------------------------------------------------------------
// Main: HMMA (mma.sync bf16 split) Gram tiles + register-fused mining.
// 256 threads, 8 warps: warp (wid&3) -> 32-row M block, (wid>>2) -> 64-col N half.
__global__ void __launch_bounds__(256, 1)
k_main(const float* __restrict__ X, const int* __restrict__ T) {
    extern __shared__ __align__(1024) char smem[];
    __shared__ int   tCol[BN];
    __shared__ float sqCol[BN];
    __shared__ float redmax[2][BM];
    __shared__ float redmin[2][BM];

    const int tid  = threadIdx.x;
    const int wid  = tid >> 5;
    const int lane = tid & 31;
    const int wm0  = (wid & 3) * 32;
    const int wn0  = (wid >> 2) * 64;
    const int row0 = blockIdx.x * BM;
    const int split = blockIdx.y;
    const int col0 = split * (N / SPLITS);
    const uint32_t sb = smem_u32(smem);

    // Per-thread row-side constants: rows = wm0 + i*16 + h*8 + (lane>>2)
    float sqr[2][2]; int trow[2][2];
    #pragma unroll
    for (int i = 0; i < 2; i++)
        #pragma unroll
        for (int h = 0; h < 2; h++) {
            int gr = row0 + wm0 + i * 16 + h * 8 + (lane >> 2);
            sqr[i][h] = g_sq[gr];
            trow[i][h] = T[gr];
        }

    // ldmatrix address precompute
    uint32_t a_rowoff[2], b_coloff[4];
    const uint32_t a_chk = (uint32_t)(lane >> 4);          // 0/1
    const uint32_t b_chk = (uint32_t)((lane >> 3) & 1);    // 0/1
    #pragma unroll
    for (int i = 0; i < 2; i++) {
        uint32_t r = wm0 + i * 16 + (lane & 7) + ((lane >> 3) & 1) * 8;
        a_rowoff[i] = r * 256 + ((r & 7) << 4) * 0 + ((r & 7) << 4);  // keep r*256; xor applied later
        a_rowoff[i] = r * 256;                                        // base; xor with chunk below
        a_rowoff[i] |= (r & 7) << 28;                                 // stash (r&7) in high bits
    }
    #pragma unroll
    for (int jj = 0; jj < 4; jj++) {
        uint32_t c = wn0 + jj * 16 + (lane & 7) + (lane >> 4) * 8;
        b_coloff[jj] = c * 256;
        b_coloff[jj] |= (c & 7) << 28;
    }

    // Prologue: A hi/lo + B tile 0 hi/lo
    cpa_tile(sb + SMA_HI, g_xhi, row0, tid);
    cpa_tile(sb + SMA_LO, g_xlo, row0, tid);
    cpa_tile(sb + SMB0,            g_xhi, col0, tid);
    cpa_tile(sb + SMB0 + 32768u,   g_xlo, col0, tid);
    CPA_COMMIT();

    float mp[2][2], mn[2][2];
    #pragma unroll
    for (int i = 0; i < 2; i++)
        #pragma unroll
        for (int h = 0; h < 2; h++) { mp[i][h] = -1.0f; mn[i][h] = FINF; }

    for (int t = 0; t < NTILES; t++) {
        const uint32_t buf = (uint32_t)(t & 1);
        if (t + 1 < NTILES) {
            int c1 = col0 + (t + 1) * BN;
            cpa_tile(sb + SMB0 + (buf ^ 1) * SMB_SZ,          g_xhi, c1, tid);
            cpa_tile(sb + SMB0 + (buf ^ 1) * SMB_SZ + 32768u, g_xlo, c1, tid);
            CPA_COMMIT();
        }
        if (tid < BN) {
            int c = col0 + t * BN + tid;
            tCol[tid] = T[c]; sqCol[tid] = g_sq[c];
        }
        if (t + 1 < NTILES) CPA_WAIT(1); else CPA_WAIT(0);
        __syncthreads();

        float acc[2][8][4];
        #pragma unroll
        for (int i = 0; i < 2; i++)
            #pragma unroll
            for (int j = 0; j < 8; j++)
                #pragma unroll
                for (int e = 0; e < 4; e++) acc[i][j][e] = 0.0f;

        #pragma unroll
        for (int p = 0; p < 3; p++) {
            const uint32_t ab = sb + (p == 2 ? SMA_LO : SMA_HI);
            const uint32_t bb = sb + SMB0 + buf * SMB_SZ + (p == 1 ? 32768u : 0u);
            #pragma unroll
            for (int ks = 0; ks < 8; ks++) {
                uint32_t a[2][4], b[4][4];
                #pragma unroll
                for (int i = 0; i < 2; i++) {
                    uint32_t ro = a_rowoff[i];
                    uint32_t chunk = (uint32_t)(2 * ks) + a_chk;
                    uint32_t addr = ab + (ro & 0x0FFFFFFFu)
                                  + ((chunk ^ (ro >> 28)) << 4);
                    ldsm4(a[i], addr);
                }
                #pragma unroll
                for (int jj = 0; jj < 4; jj++) {
                    uint32_t co = b_coloff[jj];
                    uint32_t chunk = (uint32_t)(2 * ks) + b_chk;
                    uint32_t addr = bb + (co & 0x0FFFFFFFu)
                                  + ((chunk ^ (co >> 28)) << 4);
                    ldsm4(b[jj], addr);
                }
                #pragma unroll
                for (int i = 0; i < 2; i++)
                    #pragma unroll
                    for (int jj = 0; jj < 4; jj++) {
                        mma16816(acc[i][2 * jj],     a[i], &b[jj][0]);
                        mma16816(acc[i][2 * jj + 1], a[i], &b[jj][2]);
                    }
            }
        }

        // Fused mining from register fragments.
        #pragma unroll
        for (int j = 0; j < 8; j++) {
            int cb = wn0 + j * 8 + (lane & 3) * 2;
            int tc0 = tCol[cb], tc1 = tCol[cb + 1];
            float sc0 = sqCol[cb], sc1 = sqCol[cb + 1];
            #pragma unroll
            for (int i = 0; i < 2; i++) {
                #pragma unroll
                for (int h = 0; h < 2; h++) {
                    float d0 = fmaf(-2.0f, acc[i][j][2 * h],     sqr[i][h] + sc0);
                    float d1 = fmaf(-2.0f, acc[i][j][2 * h + 1], sqr[i][h] + sc1);
                    if (trow[i][h] == tc0) mp[i][h] = fmaxf(mp[i][h], d0);
                    else                   mn[i][h] = fminf(mn[i][h], d0);
                    if (trow[i][h] == tc1) mp[i][h] = fmaxf(mp[i][h], d1);
                    else                   mn[i][h] = fminf(mn[i][h], d1);
                }
            }
        }
        __syncthreads();
    }

    // Reduce across the 4 lanes sharing each row, then across the 2 N-halves.
    #pragma unroll
    for (int i = 0; i < 2; i++)
        #pragma unroll
        for (int h = 0; h < 2; h++) {
            #pragma unroll
            for (int o = 1; o <= 2; o <<= 1) {
                mp[i][h] = fmaxf(mp[i][h], __shfl_xor_sync(0xffffffffu, mp[i][h], o));
                mn[i][h] = fminf(mn[i][h], __shfl_xor_sync(0xffffffffu, mn[i][h], o));
            }
            if ((lane & 3) == 0) {
                int r = wm0 + i * 16 + h * 8 + (lane >> 2);
                redmax[wid >> 2][r] = mp[i][h];
                redmin[wid >> 2][r] = mn[i][h];
            }
        }
    __syncthreads();
    if (tid < BM) {
        g_maxp[split][row0 + tid] = fmaxf(redmax[0][tid], redmax[1][tid]);
        g_minn[split][row0 + tid] = fminf(redmin[0][tid], redmin[1][tid]);
    }
}

// ---------------------------------------------------------------------------
__global__ void k_finalize(const float* __restrict__ X) {
    __shared__ float xs[16 * D];
    __shared__ float cnt[D * 16];
    __shared__ float terms[16];
    const int b = blockIdx.x, tid = threadIdx.x;
    const int row0 = b * 16;

    for (int i = tid; i < 16 * D; i += 256) xs[i] = X[(size_t)row0 * D + i];
    for (int i = tid; i < P * D; i += 256) {
        int k = i >> 4, c = i & 15;
        cnt[k * 16 + c] = g_cn[c * D + k];
    }
    __syncthreads();

    const int r = tid >> 4, c = tid & 15;
    float d2 = 0.0f;
    #pragma unroll 8
    for (int k = 0; k < D; k++) {
        float diff = xs[r * D + k] - cnt[k * 16 + c];
        d2 = fmaf(diff, diff, d2);
    }
    float dc = fmaxf(sqrtf(d2), EPSF);
    #pragma unroll
    for (int o = 8; o; o >>= 1) dc = fminf(dc, __shfl_xor_sync(0xffffffffu, dc, o));

    if (c == 0) {
        int row = row0 + r;
        float mpv = -1.0f, mnv = FINF;
        #pragma unroll
        for (int s = 0; s < SPLITS; s++) {
            mpv = fmaxf(mpv, g_maxp[s][row]);
            mnv = fminf(mnv, g_minn[s][row]);
        }
        float dap = sqrtf(fmaxf(mpv, EPSF));
        float dan = isinf(mnv) ? (dap + MARGINF) : sqrtf(fmaxf(mnv, EPSF));
        dan = fminf(dan, dc);
        terms[r] = fmaxf(dap - dan + MARGINF, 0.0f);
    }
    __syncthreads();
    if (tid == 0) {
        float s = 0.0f;
        #pragma unroll
        for (int i = 0; i < 16; i++) s += terms[i];
        g_partials[b] = s;
    }
}

__global__ void k_sum(float* __restrict__ out) {
    __shared__ float sh[512];
    int t = threadIdx.x;
    sh[t] = g_partials[t];
    __syncthreads();
    for (int s = 256; s; s >>= 1) {
        if (t < s) sh[t] += sh[t + s];
        __syncthreads();
    }
    if (t == 0) out[0] = sh[0] / (float)N;
}

// ---------------------------------------------------------------------------
extern "C" void kernel_launch(void* const* d_in, const int* in_sizes, int n_in,
                              void* d_out, int out_size) {
    const float* X = (const float*)d_in[0];
    const int*   T = (const int*)d_in[1];
    const float* C = (const float*)d_in[2];
    float* out = (float*)d_out;

    size_t smem = 196608;   // A hi/lo 64KB + B double buffer 128KB
    cudaFuncSetAttribute(k_main, cudaFuncAttributeMaxDynamicSharedMemorySize, (int)smem);

    k_split<<<(N * D / 4) / 256, 256>>>(X);
    k_sqnorm<<<N / 8, 256>>>(X);
    k_prep<<<1, P * 32>>>(C);
    k_main<<<dim3(N / BM, SPLITS), 256, smem>>>(X, T);
    k_finalize<<<N / 16, 256>>>(X);
    k_sum<<<1, 512>>>(out);
}

// round 5
// speedup vs baseline: 3.1925x; 1.2650x over previous
#include <cuda_runtime.h>
#include <cuda_bf16.h>
#include <cstdint>

#define N       8192
#define D       128
#define BM      128
#define BN      128
#define SPLITS  4
#define NTILES  (N / BN / SPLITS)   // 16 column tiles per split
#define P       16
#define MARGINF 1.0f
#define EPSF    1e-12f
#define FINF    __int_as_float(0x7f800000)

// smem layout (dynamic, 192KB): A hi | A lo | B buf0 (hi|lo) | B buf1 (hi|lo)
#define SMA_HI  0u
#define SMA_LO  32768u
#define SMB0    65536u
#define SMB_SZ  65536u      // hi 32KB + lo 32KB per buffer

// Scratch (no allocation allowed -> device globals)
__device__ float g_sq[N];
__device__ float g_maxp[SPLITS][N];
__device__ float g_minn[SPLITS][N];
__device__ float g_cn[P * D];
__device__ float g_partials[N / 16];
__device__ __nv_bfloat16 g_xhi[N * D];
__device__ __nv_bfloat16 g_xlo[N * D];

// ---------------------------------------------------------------------------
static __device__ __forceinline__ uint32_t smem_u32(const void* p) {
    uint32_t a;
    asm("{ .reg .u64 t; cvta.to.shared.u64 t, %1; cvt.u32.u64 %0, t; }" : "=r"(a) : "l"(p));
    return a;
}
static __device__ __forceinline__ void ldsm4(uint32_t* r, uint32_t addr) {
    asm volatile("ldmatrix.sync.aligned.m8n8.x4.shared.b16 {%0,%1,%2,%3}, [%4];"
                 : "=r"(r[0]), "=r"(r[1]), "=r"(r[2]), "=r"(r[3]) : "r"(addr));
}
static __device__ __forceinline__ void mma16816(float* c, const uint32_t* a,
                                                const uint32_t* b) {
    asm volatile("mma.sync.aligned.m16n8k16.row.col.f32.bf16.bf16.f32 "
                 "{%0,%1,%2,%3}, {%4,%5,%6,%7}, {%8,%9}, {%0,%1,%2,%3};"
                 : "+f"(c[0]), "+f"(c[1]), "+f"(c[2]), "+f"(c[3])
                 : "r"(a[0]), "r"(a[1]), "r"(a[2]), "r"(a[3]), "r"(b[0]), "r"(b[1]));
}
static __device__ __forceinline__ void cpa16(uint32_t dst, const void* src) {
    asm volatile("cp.async.cg.shared.global [%0], [%1], 16;" :: "r"(dst), "l"(src) : "memory");
}
#define CPA_COMMIT() asm volatile("cp.async.commit_group;" ::: "memory")
#define CPA_WAIT(n)  asm volatile("cp.async.wait_group %0;" :: "n"(n) : "memory")

// 128x128 bf16 tile -> smem, row-major 256B rows, 16B-chunk xor swizzle.
static __device__ __forceinline__ void cpa_tile(uint32_t dst_s,
                                                const __nv_bfloat16* src,
                                                int row0, int tid) {
    const char* base = (const char*)(src + (size_t)row0 * D);
    #pragma unroll
    for (int i = 0; i < 8; i++) {
        int idx = tid + i * 256;
        int r = idx >> 4, c = idx & 15;
        uint32_t off = (uint32_t)r * 256 + (uint32_t)((c ^ (r & 7)) << 4);
        cpa16(dst_s + off, base + (size_t)r * 256 + c * 16);
    }
}

// ---------------------------------------------------------------------------
// Split fp32 -> bf16 hi/lo pair (hi = rn(x), lo = rn(x - hi)).
__global__ void k_split(const float* __restrict__ X) {
    int i = blockIdx.x * blockDim.x + threadIdx.x;
    float4 v = ((const float4*)X)[i];
    __nv_bfloat16 h0 = __float2bfloat16(v.x), h1 = __float2bfloat16(v.y);
    __nv_bfloat16 h2 = __float2bfloat16(v.z), h3 = __float2bfloat16(v.w);
    __nv_bfloat16 l0 = __float2bfloat16(v.x - __bfloat162float(h0));
    __nv_bfloat16 l1 = __float2bfloat16(v.y - __bfloat162float(h1));
    __nv_bfloat16 l2 = __float2bfloat16(v.z - __bfloat162float(h2));
    __nv_bfloat16 l3 = __float2bfloat16(v.w - __bfloat162float(h3));
    ((__nv_bfloat162*)g_xhi)[2*i]   = __nv_bfloat162(h0, h1);
    ((__nv_bfloat162*)g_xhi)[2*i+1] = __nv_bfloat162(h2, h3);
    ((__nv_bfloat162*)g_xlo)[2*i]   = __nv_bfloat162(l0, l1);
    ((__nv_bfloat162*)g_xlo)[2*i+1] = __nv_bfloat162(l2, l3);
}

__global__ void k_sqnorm(const float* __restrict__ X) {
    int w = (blockIdx.x * blockDim.x + threadIdx.x) >> 5;
    int lane = threadIdx.x & 31;
    if (w >= N) return;
    const float4* x4 = (const float4*)X + (size_t)w * (D / 4);
    float4 v = x4[lane];
    float s = v.x * v.x + v.y * v.y + v.z * v.z + v.w * v.w;
    #pragma unroll
    for (int o = 16; o; o >>= 1) s += __shfl_xor_sync(0xffffffffu, s, o);
    if (lane == 0) g_sq[w] = s;
}

__global__ void k_prep(const float* __restrict__ C) {
    int w = threadIdx.x >> 5;
    int lane = threadIdx.x & 31;
    if (w >= P) return;
    const float4* c4 = (const float4*)(C + (size_t)w * D);
    float4 v = c4[lane];
    float s = v.x * v.x + v.y * v.y + v.z * v.z + v.w * v.w;
    #pragma unroll
    for (int o = 16; o; o >>= 1) s += __shfl_xor_sync(0xffffffffu, s, o);
    float inv = 1.0f / sqrtf(s);
    float* dst = g_cn + (size_t)w * D + lane * 4;
    dst[0] = v.x * inv; dst[1] = v.y * inv; dst[2] = v.z * inv; dst[3] = v.w * inv;
}

// ---------------------------------------------------------------------------
// Main: HMMA split-bf16 Gram tiles, load-once fragments, 1 sync/tile.
// 256 threads, 8 warps: warp (wid&3) -> 32-row M block, (wid>>2) -> 64-col N half.
__global__ void __launch_bounds__(256, 1)
k_main(const float* __restrict__ X, const int* __restrict__ T) {
    extern __shared__ __align__(1024) char smem[];
    __shared__ int   tCol[2][BN];
    __shared__ float sqCol[2][BN];
    __shared__ float redmax[2][BM];
    __shared__ float redmin[2][BM];

    const int tid  = threadIdx.x;
    const int wid  = tid >> 5;
    const int lane = tid & 31;
    const int wm0  = (wid & 3) * 32;
    const int wn0  = (wid >> 2) * 64;
    const int row0 = blockIdx.x * BM;
    const int split = blockIdx.y;
    const int col0 = split * (N / SPLITS);
    const uint32_t sb = smem_u32(smem);

    // Per-thread row-side constants: rows = wm0 + i*16 + h*8 + (lane>>2)
    float sqr[2][2]; int trow[2][2];
    #pragma unroll
    for (int i = 0; i < 2; i++)
        #pragma unroll
        for (int h = 0; h < 2; h++) {
            int gr = row0 + wm0 + i * 16 + h * 8 + (lane >> 2);
            sqr[i][h] = g_sq[gr];
            trow[i][h] = T[gr];
        }

    // ldmatrix address precompute: base row/col offset + swizzle key in bits 28+
    uint32_t a_rowoff[2], b_coloff[4];
    const uint32_t a_chk = (uint32_t)(lane >> 4);          // 0/1
    const uint32_t b_chk = (uint32_t)((lane >> 3) & 1);    // 0/1
    #pragma unroll
    for (int i = 0; i < 2; i++) {
        uint32_t r = wm0 + i * 16 + (lane & 7) + ((lane >> 3) & 1) * 8;
        a_rowoff[i] = (r * 256) | ((r & 7) << 28);
    }
    #pragma unroll
    for (int jj = 0; jj < 4; jj++) {
        uint32_t c = wn0 + jj * 16 + (lane & 7) + (lane >> 4) * 8;
        b_coloff[jj] = (c * 256) | ((c & 7) << 28);
    }

    // Prologue: A hi/lo + B tile 0 hi/lo + labels(0)
    cpa_tile(sb + SMA_HI, g_xhi, row0, tid);
    cpa_tile(sb + SMA_LO, g_xlo, row0, tid);
    cpa_tile(sb + SMB0,          g_xhi, col0, tid);
    cpa_tile(sb + SMB0 + 32768u, g_xlo, col0, tid);
    CPA_COMMIT();
    if (tid < BN) { tCol[0][tid] = T[col0 + tid]; sqCol[0][tid] = g_sq[col0 + tid]; }

    float mp[2][2], mn[2][2];
    #pragma unroll
    for (int i = 0; i < 2; i++)
        #pragma unroll
        for (int h = 0; h < 2; h++) { mp[i][h] = -1.0f; mn[i][h] = FINF; }

    for (int t = 0; t < NTILES; t++) {
        const uint32_t buf = (uint32_t)(t & 1);
        CPA_WAIT(0);            // tile t resident
        __syncthreads();        // all warps done with iter t-1 consumers

        // Producers for tile t+1 go into buf^1 (its last readers passed the sync).
        if (t + 1 < NTILES) {
            int c1 = col0 + (t + 1) * BN;
            cpa_tile(sb + SMB0 + (buf ^ 1) * SMB_SZ,          g_xhi, c1, tid);
            cpa_tile(sb + SMB0 + (buf ^ 1) * SMB_SZ + 32768u, g_xlo, c1, tid);
            CPA_COMMIT();
            if (tid < BN) {
                int c = c1 + tid;
                tCol[buf ^ 1][tid] = T[c]; sqCol[buf ^ 1][tid] = g_sq[c];
            }
        }

        float acc[2][8][4];
        #pragma unroll
        for (int i = 0; i < 2; i++)
            #pragma unroll
            for (int j = 0; j < 8; j++)
                #pragma unroll
                for (int e = 0; e < 4; e++) acc[i][j][e] = 0.0f;

        const uint32_t ab_hi = sb + SMA_HI;
        const uint32_t ab_lo = sb + SMA_LO;
        const uint32_t bb_hi = sb + SMB0 + buf * SMB_SZ;
        const uint32_t bb_lo = bb_hi + 32768u;

        #pragma unroll
        for (int ks = 0; ks < 8; ks++) {
            uint32_t a_hi[2][4], a_lo[2][4], b_hi[4][4], b_lo[4][4];
            const uint32_t achunk = (uint32_t)(2 * ks) + a_chk;
            const uint32_t bchunk = (uint32_t)(2 * ks) + b_chk;
            #pragma unroll
            for (int i = 0; i < 2; i++) {
                uint32_t ro = a_rowoff[i];
                uint32_t off = (ro & 0x0FFFFFFFu) + ((achunk ^ (ro >> 28)) << 4);
                ldsm4(a_hi[i], ab_hi + off);
                ldsm4(a_lo[i], ab_lo + off);
            }
            #pragma unroll
            for (int jj = 0; jj < 4; jj++) {
                uint32_t co = b_coloff[jj];
                uint32_t off = (co & 0x0FFFFFFFu) + ((bchunk ^ (co >> 28)) << 4);
                ldsm4(b_hi[jj], bb_hi + off);
                ldsm4(b_lo[jj], bb_lo + off);
            }
            // 48 independent MMAs: hi*hi + hi*lo + lo*hi
            #pragma unroll
            for (int i = 0; i < 2; i++)
                #pragma unroll
                for (int jj = 0; jj < 4; jj++) {
                    mma16816(acc[i][2 * jj],     a_hi[i], &b_hi[jj][0]);
                    mma16816(acc[i][2 * jj + 1], a_hi[i], &b_hi[jj][2]);
                    mma16816(acc[i][2 * jj],     a_hi[i], &b_lo[jj][0]);
                    mma16816(acc[i][2 * jj + 1], a_hi[i], &b_lo[jj][2]);
                    mma16816(acc[i][2 * jj],     a_lo[i], &b_hi[jj][0]);
                    mma16816(acc[i][2 * jj + 1], a_lo[i], &b_hi[jj][2]);
                }
        }

        // Fused mining from register fragments.
        #pragma unroll
        for (int j = 0; j < 8; j++) {
            int cb = wn0 + j * 8 + (lane & 3) * 2;
            int tc0 = tCol[buf][cb], tc1 = tCol[buf][cb + 1];
            float sc0 = sqCol[buf][cb], sc1 = sqCol[buf][cb + 1];
            #pragma unroll
            for (int i = 0; i < 2; i++) {
                #pragma unroll
                for (int h = 0; h < 2; h++) {
                    float d0 = fmaf(-2.0f, acc[i][j][2 * h],     sqr[i][h] + sc0);
                    float d1 = fmaf(-2.0f, acc[i][j][2 * h + 1], sqr[i][h] + sc1);
                    if (trow[i][h] == tc0) mp[i][h] = fmaxf(mp[i][h], d0);
                    else                   mn[i][h] = fminf(mn[i][h], d0);
                    if (trow[i][h] == tc1) mp[i][h] = fmaxf(mp[i][h], d1);
                    else                   mn[i][h] = fminf(mn[i][h], d1);
                }
            }
        }
    }

    // Reduce across the 4 lanes sharing each row, then across the 2 N-halves.
    #pragma unroll
    for (int i = 0; i < 2; i++)
        #pragma unroll
        for (int h = 0; h < 2; h++) {
            #pragma unroll
            for (int o = 1; o <= 2; o <<= 1) {
                mp[i][h] = fmaxf(mp[i][h], __shfl_xor_sync(0xffffffffu, mp[i][h], o));
                mn[i][h] = fminf(mn[i][h], __shfl_xor_sync(0xffffffffu, mn[i][h], o));
            }
            if ((lane & 3) == 0) {
                int r = wm0 + i * 16 + h * 8 + (lane >> 2);
                redmax[wid >> 2][r] = mp[i][h];
                redmin[wid >> 2][r] = mn[i][h];
            }
        }
    __syncthreads();
    if (tid < BM) {
        g_maxp[split][row0 + tid] = fmaxf(redmax[0][tid], redmax[1][tid]);
        g_minn[split][row0 + tid] = fminf(redmin[0][tid], redmin[1][tid]);
    }
}

// ---------------------------------------------------------------------------
__global__ void k_finalize(const float* __restrict__ X) {
    __shared__ float xs[16 * D];
    __shared__ float cnt[D * 16];
    __shared__ float terms[16];
    const int b = blockIdx.x, tid = threadIdx.x;
    const int row0 = b * 16;

    for (int i = tid; i < 16 * D; i += 256) xs[i] = X[(size_t)row0 * D + i];
    for (int i = tid; i < P * D; i += 256) {
        int k = i >> 4, c = i & 15;
        cnt[k * 16 + c] = g_cn[c * D + k];
    }
    __syncthreads();

    const int r = tid >> 4, c = tid & 15;
    float d2 = 0.0f;
    #pragma unroll 8
    for (int k = 0; k < D; k++) {
        float diff = xs[r * D + k] - cnt[k * 16 + c];
        d2 = fmaf(diff, diff, d2);
    }
    float dc = fmaxf(sqrtf(d2), EPSF);
    #pragma unroll
    for (int o = 8; o; o >>= 1) dc = fminf(dc, __shfl_xor_sync(0xffffffffu, dc, o));

    if (c == 0) {
        int row = row0 + r;
        float mpv = -1.0f, mnv = FINF;
        #pragma unroll
        for (int s = 0; s < SPLITS; s++) {
            mpv = fmaxf(mpv, g_maxp[s][row]);
            mnv = fminf(mnv, g_minn[s][row]);
        }
        float dap = sqrtf(fmaxf(mpv, EPSF));
        float dan = isinf(mnv) ? (dap + MARGINF) : sqrtf(fmaxf(mnv, EPSF));
        dan = fminf(dan, dc);
        terms[r] = fmaxf(dap - dan + MARGINF, 0.0f);
    }
    __syncthreads();
    if (tid == 0) {
        float s = 0.0f;
        #pragma unroll
        for (int i = 0; i < 16; i++) s += terms[i];
        g_partials[b] = s;
    }
}

__global__ void k_sum(float* __restrict__ out) {
    __shared__ float sh[512];
    int t = threadIdx.x;
    sh[t] = g_partials[t];
    __syncthreads();
    for (int s = 256; s; s >>= 1) {
        if (t < s) sh[t] += sh[t + s];
        __syncthreads();
    }
    if (t == 0) out[0] = sh[0] / (float)N;
}

// ---------------------------------------------------------------------------
extern "C" void kernel_launch(void* const* d_in, const int* in_sizes, int n_in,
                              void* d_out, int out_size) {
    const float* X = (const float*)d_in[0];
    const int*   T = (const int*)d_in[1];
    const float* C = (const float*)d_in[2];
    float* out = (float*)d_out;

    size_t smem = 196608;   // A hi/lo 64KB + B double buffer 128KB
    cudaFuncSetAttribute(k_main, cudaFuncAttributeMaxDynamicSharedMemorySize, (int)smem);

    k_split<<<(N * D / 4) / 256, 256>>>(X);
    k_sqnorm<<<N / 8, 256>>>(X);
    k_prep<<<1, P * 32>>>(C);
    k_main<<<dim3(N / BM, SPLITS), 256, smem>>>(X, T);
    k_finalize<<<N / 16, 256>>>(X);
    k_sum<<<1, 512>>>(out);
}

// round 6
// speedup vs baseline: 4.6281x; 1.4497x over previous
#include <cuda_runtime.h>
#include <cuda_bf16.h>
#include <cstdint>

#define N       8192
#define D       128
#define BM      128
#define BN      128
#define NB      64          // number of 128-row blocks
#define P       16
#define MARGINF 1.0f
#define EPSF    1e-12f
#define FINF    __int_as_float(0x7f800000)
#define INFBITS 0x7f800000

// smem layout (dynamic, 192KB): A hi | A lo | B buf0 (hi|lo) | B buf1 (hi|lo)
#define SMA_HI  0u
#define SMA_LO  32768u
#define SMB0    65536u
#define SMB_SZ  65536u      // hi 32KB + lo 32KB per buffer

// Scratch (no allocation allowed -> device globals)
__device__ float g_sq[N];
__device__ int   g_maxp[N];     // float bits, mined via deterministic atomics
__device__ int   g_minn[N];
__device__ float g_cn[P * D];
__device__ float g_partials[N / 16];
__device__ __nv_bfloat16 g_xhi[N * D];
__device__ __nv_bfloat16 g_xlo[N * D];

// ---------------------------------------------------------------------------
static __device__ __forceinline__ uint32_t smem_u32(const void* p) {
    uint32_t a;
    asm("{ .reg .u64 t; cvta.to.shared.u64 t, %1; cvt.u32.u64 %0, t; }" : "=r"(a) : "l"(p));
    return a;
}
static __device__ __forceinline__ void ldsm4(uint32_t* r, uint32_t addr) {
    asm volatile("ldmatrix.sync.aligned.m8n8.x4.shared.b16 {%0,%1,%2,%3}, [%4];"
                 : "=r"(r[0]), "=r"(r[1]), "=r"(r[2]), "=r"(r[3]) : "r"(addr));
}
static __device__ __forceinline__ void mma16816(float* c, const uint32_t* a,
                                                const uint32_t* b) {
    asm volatile("mma.sync.aligned.m16n8k16.row.col.f32.bf16.bf16.f32 "
                 "{%0,%1,%2,%3}, {%4,%5,%6,%7}, {%8,%9}, {%0,%1,%2,%3};"
                 : "+f"(c[0]), "+f"(c[1]), "+f"(c[2]), "+f"(c[3])
                 : "r"(a[0]), "r"(a[1]), "r"(a[2]), "r"(a[3]), "r"(b[0]), "r"(b[1]));
}
static __device__ __forceinline__ void cpa16(uint32_t dst, const void* src) {
    asm volatile("cp.async.cg.shared.global [%0], [%1], 16;" :: "r"(dst), "l"(src) : "memory");
}
#define CPA_COMMIT() asm volatile("cp.async.commit_group;" ::: "memory")
#define CPA_WAIT(n)  asm volatile("cp.async.wait_group %0;" :: "n"(n) : "memory")

// 128x128 bf16 tile -> smem, row-major 256B rows, 16B-chunk xor swizzle.
static __device__ __forceinline__ void cpa_tile(uint32_t dst_s,
                                                const __nv_bfloat16* src,
                                                int row0, int tid) {
    const char* base = (const char*)(src + (size_t)row0 * D);
    #pragma unroll
    for (int i = 0; i < 8; i++) {
        int idx = tid + i * 256;
        int r = idx >> 4, c = idx & 15;
        uint32_t off = (uint32_t)r * 256 + (uint32_t)((c ^ (r & 7)) << 4);
        cpa16(dst_s + off, base + (size_t)r * 256 + c * 16);
    }
}

// ---------------------------------------------------------------------------
// Split fp32 -> bf16 hi/lo pair (hi = rn(x), lo = rn(x - hi)).
__global__ void k_split(const float* __restrict__ X) {
    int i = blockIdx.x * blockDim.x + threadIdx.x;
    float4 v = ((const float4*)X)[i];
    __nv_bfloat16 h0 = __float2bfloat16(v.x), h1 = __float2bfloat16(v.y);
    __nv_bfloat16 h2 = __float2bfloat16(v.z), h3 = __float2bfloat16(v.w);
    __nv_bfloat16 l0 = __float2bfloat16(v.x - __bfloat162float(h0));
    __nv_bfloat16 l1 = __float2bfloat16(v.y - __bfloat162float(h1));
    __nv_bfloat16 l2 = __float2bfloat16(v.z - __bfloat162float(h2));
    __nv_bfloat16 l3 = __float2bfloat16(v.w - __bfloat162float(h3));
    ((__nv_bfloat162*)g_xhi)[2*i]   = __nv_bfloat162(h0, h1);
    ((__nv_bfloat162*)g_xhi)[2*i+1] = __nv_bfloat162(h2, h3);
    ((__nv_bfloat162*)g_xlo)[2*i]   = __nv_bfloat162(l0, l1);
    ((__nv_bfloat162*)g_xlo)[2*i+1] = __nv_bfloat162(l2, l3);
}

// Row squared norms + init the mined arrays.
__global__ void k_sqnorm(const float* __restrict__ X) {
    int w = (blockIdx.x * blockDim.x + threadIdx.x) >> 5;
    int lane = threadIdx.x & 31;
    if (w >= N) return;
    const float4* x4 = (const float4*)X + (size_t)w * (D / 4);
    float4 v = x4[lane];
    float s = v.x * v.x + v.y * v.y + v.z * v.z + v.w * v.w;
    #pragma unroll
    for (int o = 16; o; o >>= 1) s += __shfl_xor_sync(0xffffffffu, s, o);
    if (lane == 0) { g_sq[w] = s; g_maxp[w] = 0; g_minn[w] = INFBITS; }
}

__global__ void k_prep(const float* __restrict__ C) {
    int w = threadIdx.x >> 5;
    int lane = threadIdx.x & 31;
    if (w >= P) return;
    const float4* c4 = (const float4*)(C + (size_t)w * D);
    float4 v = c4[lane];
    float s = v.x * v.x + v.y * v.y + v.z * v.z + v.w * v.w;
    #pragma unroll
    for (int o = 16; o; o >>= 1) s += __shfl_xor_sync(0xffffffffu, s, o);
    float inv = 1.0f / sqrtf(s);
    float* dst = g_cn + (size_t)w * D + lane * 4;
    dst[0] = v.x * inv; dst[1] = v.y * inv; dst[2] = v.z * inv; dst[3] = v.w * inv;
}

// ---------------------------------------------------------------------------
// Symmetric mining: block (I, s) computes tiles (I, (I+k)%64), k in its chunk.
// Every unordered block pair has circular distance <= 32 -> covered; duplicate
// coverage is harmless for max/min. Each tile mines rows of I AND (via
// symmetry) rows of J from the column direction.
__global__ void __launch_bounds__(256, 1)
k_main(const float* __restrict__ X, const int* __restrict__ T) {
    extern __shared__ __align__(1024) char smem[];
    __shared__ int   tCol[2][BN];
    __shared__ float sqCol[2][BN];
    __shared__ float redmax[2][BM];
    __shared__ float redmin[2][BM];
    __shared__ float s_cmax[4][BN];
    __shared__ float s_cmin[4][BN];
    __shared__ int   s_J[2];

    const int tid  = threadIdx.x;
    const int wid  = tid >> 5;
    const int lane = tid & 31;
    const int mw   = wid & 3;          // M-warp index (32-row block)
    const int nh   = wid >> 2;         // N half (64 cols)
    const int wm0  = mw * 32;
    const int wn0  = nh * 64;
    const int I    = blockIdx.x;
    const int sch  = blockIdx.y;       // 0: k=0..16, 1: k=17..32
    const int kbeg = sch ? 17 : 0;
    const int kcnt = sch ? 16 : 17;
    const int row0 = I * BM;
    const uint32_t sb = smem_u32(smem);

    // Per-thread row-side constants: rows = wm0 + i*16 + h*8 + (lane>>2)
    float sqr[2][2]; int trow[2][2];
    #pragma unroll
    for (int i = 0; i < 2; i++)
        #pragma unroll
        for (int h = 0; h < 2; h++) {
            int gr = row0 + wm0 + i * 16 + h * 8 + (lane >> 2);
            sqr[i][h] = g_sq[gr];
            trow[i][h] = T[gr];
        }

    // ldmatrix address precompute: base offset + swizzle key in bits 28+
    uint32_t a_rowoff[2], b_coloff[4];
    const uint32_t a_chk = (uint32_t)(lane >> 4);
    const uint32_t b_chk = (uint32_t)((lane >> 3) & 1);
    #pragma unroll
    for (int i = 0; i < 2; i++) {
        uint32_t r = wm0 + i * 16 + (lane & 7) + ((lane >> 3) & 1) * 8;
        a_rowoff[i] = (r * 256) | ((r & 7) << 28);
    }
    #pragma unroll
    for (int jj = 0; jj < 4; jj++) {
        uint32_t c = wn0 + jj * 16 + (lane & 7) + (lane >> 4) * 8;
        b_coloff[jj] = (c * 256) | ((c & 7) << 28);
    }

    // Prologue: A hi/lo + B tile(k=kbeg) + labels
    cpa_tile(sb + SMA_HI, g_xhi, row0, tid);
    cpa_tile(sb + SMA_LO, g_xlo, row0, tid);
    {
        int J0 = (I + kbeg) & (NB - 1);
        cpa_tile(sb + SMB0,          g_xhi, J0 * BN, tid);
        cpa_tile(sb + SMB0 + 32768u, g_xlo, J0 * BN, tid);
        if (tid < BN) { tCol[0][tid] = T[J0 * BN + tid]; sqCol[0][tid] = g_sq[J0 * BN + tid]; }
        if (tid == 0) s_J[0] = J0;
    }
    CPA_COMMIT();

    float mp[2][2], mn[2][2];
    #pragma unroll
    for (int i = 0; i < 2; i++)
        #pragma unroll
        for (int h = 0; h < 2; h++) { mp[i][h] = -1.0f; mn[i][h] = FINF; }

    for (int t = 0; t < kcnt; t++) {
        const uint32_t buf = (uint32_t)(t & 1);
        CPA_WAIT(0);
        __syncthreads();        // tile t resident; prev-iter smem readers done

        if (t + 1 < kcnt) {
            int J1 = (I + kbeg + t + 1) & (NB - 1);
            cpa_tile(sb + SMB0 + (buf ^ 1) * SMB_SZ,          g_xhi, J1 * BN, tid);
            cpa_tile(sb + SMB0 + (buf ^ 1) * SMB_SZ + 32768u, g_xlo, J1 * BN, tid);
            CPA_COMMIT();
            if (tid < BN) {
                tCol[buf ^ 1][tid] = T[J1 * BN + tid];
                sqCol[buf ^ 1][tid] = g_sq[J1 * BN + tid];
            }
            if (tid == 0) s_J[buf ^ 1] = J1;
        }

        float acc[2][8][4];
        #pragma unroll
        for (int i = 0; i < 2; i++)
            #pragma unroll
            for (int j = 0; j < 8; j++)
                #pragma unroll
                for (int e = 0; e < 4; e++) acc[i][j][e] = 0.0f;

        const uint32_t ab_hi = sb + SMA_HI;
        const uint32_t ab_lo = sb + SMA_LO;
        const uint32_t bb_hi = sb + SMB0 + buf * SMB_SZ;
        const uint32_t bb_lo = bb_hi + 32768u;

        #pragma unroll
        for (int ks = 0; ks < 8; ks++) {
            uint32_t a_hi[2][4], a_lo[2][4], b_hi[4][4], b_lo[4][4];
            const uint32_t achunk = (uint32_t)(2 * ks) + a_chk;
            const uint32_t bchunk = (uint32_t)(2 * ks) + b_chk;
            #pragma unroll
            for (int i = 0; i < 2; i++) {
                uint32_t ro = a_rowoff[i];
                uint32_t off = (ro & 0x0FFFFFFFu) + ((achunk ^ (ro >> 28)) << 4);
                ldsm4(a_hi[i], ab_hi + off);
                ldsm4(a_lo[i], ab_lo + off);
            }
            #pragma unroll
            for (int jj = 0; jj < 4; jj++) {
                uint32_t co = b_coloff[jj];
                uint32_t off = (co & 0x0FFFFFFFu) + ((bchunk ^ (co >> 28)) << 4);
                ldsm4(b_hi[jj], bb_hi + off);
                ldsm4(b_lo[jj], bb_lo + off);
            }
            #pragma unroll
            for (int i = 0; i < 2; i++)
                #pragma unroll
                for (int jj = 0; jj < 4; jj++) {
                    mma16816(acc[i][2 * jj],     a_hi[i], &b_hi[jj][0]);
                    mma16816(acc[i][2 * jj + 1], a_hi[i], &b_hi[jj][2]);
                    mma16816(acc[i][2 * jj],     a_hi[i], &b_lo[jj][0]);
                    mma16816(acc[i][2 * jj + 1], a_hi[i], &b_lo[jj][2]);
                    mma16816(acc[i][2 * jj],     a_lo[i], &b_hi[jj][0]);
                    mma16816(acc[i][2 * jj + 1], a_lo[i], &b_hi[jj][2]);
                }
        }

        // Fused mining: row stats (registers, persistent) + col stats (per tile).
        float cmax[8][2], cmin[8][2];
        #pragma unroll
        for (int j = 0; j < 8; j++) { cmax[j][0] = cmax[j][1] = -1.0f;
                                      cmin[j][0] = cmin[j][1] = FINF; }
        #pragma unroll
        for (int j = 0; j < 8; j++) {
            int cb = wn0 + j * 8 + (lane & 3) * 2;
            int tc0 = tCol[buf][cb], tc1 = tCol[buf][cb + 1];
            float sc0 = sqCol[buf][cb], sc1 = sqCol[buf][cb + 1];
            #pragma unroll
            for (int i = 0; i < 2; i++)
                #pragma unroll
                for (int h = 0; h < 2; h++) {
                    float d0 = fmaxf(fmaf(-2.0f, acc[i][j][2 * h],     sqr[i][h] + sc0), 0.0f);
                    float d1 = fmaxf(fmaf(-2.0f, acc[i][j][2 * h + 1], sqr[i][h] + sc1), 0.0f);
                    if (trow[i][h] == tc0) { mp[i][h] = fmaxf(mp[i][h], d0);
                                             cmax[j][0] = fmaxf(cmax[j][0], d0); }
                    else                   { mn[i][h] = fminf(mn[i][h], d0);
                                             cmin[j][0] = fminf(cmin[j][0], d0); }
                    if (trow[i][h] == tc1) { mp[i][h] = fmaxf(mp[i][h], d1);
                                             cmax[j][1] = fmaxf(cmax[j][1], d1); }
                    else                   { mn[i][h] = fminf(mn[i][h], d1);
                                             cmin[j][1] = fminf(cmin[j][1], d1); }
                }
        }
        // Butterfly over the 8 row-lane-groups (lane bits 2..4).
        #pragma unroll
        for (int j = 0; j < 8; j++)
            #pragma unroll
            for (int e = 0; e < 2; e++) {
                #pragma unroll
                for (int o = 4; o <= 16; o <<= 1) {
                    cmax[j][e] = fmaxf(cmax[j][e], __shfl_xor_sync(0xffffffffu, cmax[j][e], o));
                    cmin[j][e] = fminf(cmin[j][e], __shfl_xor_sync(0xffffffffu, cmin[j][e], o));
                }
            }
        if (lane < 4) {
            #pragma unroll
            for (int j = 0; j < 8; j++)
                #pragma unroll
                for (int e = 0; e < 2; e++) {
                    int c = wn0 + j * 8 + lane * 2 + e;
                    s_cmax[mw][c] = cmax[j][e];
                    s_cmin[mw][c] = cmin[j][e];
                }
        }
        __syncthreads();
        if (tid < BN) {
            float vmax = fmaxf(fmaxf(s_cmax[0][tid], s_cmax[1][tid]),
                               fmaxf(s_cmax[2][tid], s_cmax[3][tid]));
            float vmin = fminf(fminf(s_cmin[0][tid], s_cmin[1][tid]),
                               fminf(s_cmin[2][tid], s_cmin[3][tid]));
            int gcol = s_J[buf] * BN + tid;
            atomicMax(&g_maxp[gcol], __float_as_int(vmax));
            atomicMin(&g_minn[gcol], __float_as_int(vmin));
        }
    }

    // Row stats: reduce over the 4 lanes sharing each row, then the 2 N-halves.
    #pragma unroll
    for (int i = 0; i < 2; i++)
        #pragma unroll
        for (int h = 0; h < 2; h++) {
            #pragma unroll
            for (int o = 1; o <= 2; o <<= 1) {
                mp[i][h] = fmaxf(mp[i][h], __shfl_xor_sync(0xffffffffu, mp[i][h], o));
                mn[i][h] = fminf(mn[i][h], __shfl_xor_sync(0xffffffffu, mn[i][h], o));
            }
            if ((lane & 3) == 0) {
                int r = wm0 + i * 16 + h * 8 + (lane >> 2);
                redmax[nh][r] = mp[i][h];
                redmin[nh][r] = mn[i][h];
            }
        }
    __syncthreads();
    if (tid < BM) {
        float rmax = fmaxf(redmax[0][tid], redmax[1][tid]);
        float rmin = fminf(redmin[0][tid], redmin[1][tid]);
        atomicMax(&g_maxp[row0 + tid], __float_as_int(rmax));
        atomicMin(&g_minn[row0 + tid], __float_as_int(rmin));
    }
}

// ---------------------------------------------------------------------------
__global__ void k_finalize(const float* __restrict__ X) {
    __shared__ float xs[16 * D];
    __shared__ float cnt[D * 16];
    __shared__ float terms[16];
    const int b = blockIdx.x, tid = threadIdx.x;
    const int row0 = b * 16;

    for (int i = tid; i < 16 * D; i += 256) xs[i] = X[(size_t)row0 * D + i];
    for (int i = tid; i < P * D; i += 256) {
        int k = i >> 4, c = i & 15;
        cnt[k * 16 + c] = g_cn[c * D + k];
    }
    __syncthreads();

    const int r = tid >> 4, c = tid & 15;
    float d2 = 0.0f;
    #pragma unroll 8
    for (int k = 0; k < D; k++) {
        float diff = xs[r * D + k] - cnt[k * 16 + c];
        d2 = fmaf(diff, diff, d2);
    }
    float dc = fmaxf(sqrtf(d2), EPSF);
    #pragma unroll
    for (int o = 8; o; o >>= 1) dc = fminf(dc, __shfl_xor_sync(0xffffffffu, dc, o));

    if (c == 0) {
        int row = row0 + r;
        float mpv = __int_as_float(g_maxp[row]);
        float mnv = __int_as_float(g_minn[row]);
        float dap = sqrtf(fmaxf(mpv, EPSF));
        float dan = isinf(mnv) ? (dap + MARGINF) : sqrtf(fmaxf(mnv, EPSF));
        dan = fminf(dan, dc);
        terms[r] = fmaxf(dap - dan + MARGINF, 0.0f);
    }
    __syncthreads();
    if (tid == 0) {
        float s = 0.0f;
        #pragma unroll
        for (int i = 0; i < 16; i++) s += terms[i];
        g_partials[b] = s;
    }
}

__global__ void k_sum(float* __restrict__ out) {
    __shared__ float sh[512];
    int t = threadIdx.x;
    sh[t] = g_partials[t];
    __syncthreads();
    for (int s = 256; s; s >>= 1) {
        if (t < s) sh[t] += sh[t + s];
        __syncthreads();
    }
    if (t == 0) out[0] = sh[0] / (float)N;
}

// ---------------------------------------------------------------------------
extern "C" void kernel_launch(void* const* d_in, const int* in_sizes, int n_in,
                              void* d_out, int out_size) {
    const float* X = (const float*)d_in[0];
    const int*   T = (const int*)d_in[1];
    const float* C = (const float*)d_in[2];
    float* out = (float*)d_out;

    size_t smem = 196608;   // A hi/lo 64KB + B double buffer 128KB
    cudaFuncSetAttribute(k_main, cudaFuncAttributeMaxDynamicSharedMemorySize, (int)smem);

    k_split<<<(N * D / 4) / 256, 256>>>(X);
    k_sqnorm<<<N / 8, 256>>>(X);
    k_prep<<<1, P * 32>>>(C);
    k_main<<<dim3(NB, 2), 256, smem>>>(X, T);
    k_finalize<<<N / 16, 256>>>(X);
    k_sum<<<1, 512>>>(out);
}